// round 1
// baseline (speedup 1.0000x reference)
#include <cuda_runtime.h>
#include <math.h>

#define MB   2
#define SEQ  2048
#define DM   4096
#define NH   16
#define HDIM 256
#define ROTD 64

// Scratch: Q,K,V in [B,H,S,HD]; CTX in [B,S,D]
__device__ float g_Q[(size_t)MB * NH * SEQ * HDIM];
__device__ float g_K[(size_t)MB * NH * SEQ * HDIM];
__device__ float g_V[(size_t)MB * NH * SEQ * HDIM];
__device__ float g_CTX[(size_t)MB * SEQ * DM];

// ---------------------------------------------------------------------------
// SGEMM: C[M,N] = A[M,K] @ B[K,N], M=N=K=4096, fp32.
// 128x128 block tile, BK=8, 256 threads, 8x8 per thread, register prefetch.
// mode 0: C row-major [M,N] (plain). mode 1: scatter to [B,H,S,HD].
// ---------------------------------------------------------------------------
__global__ void __launch_bounds__(256) sgemm_kernel(
    const float* __restrict__ A, const float* __restrict__ B,
    float* __restrict__ C, int mode)
{
    const int K = DM, N = DM;
    __shared__ float As[8][128];
    __shared__ float Bs[8][128];

    int bm = blockIdx.y * 128;
    int bn = blockIdx.x * 128;
    int tid = threadIdx.x;
    int tx = tid & 15;        // 0..15 -> N
    int ty = tid >> 4;        // 0..15 -> M

    int a_row = tid >> 1;           // 0..127
    int a_col = (tid & 1) << 2;     // 0 or 4
    int b_row = tid >> 5;           // 0..7
    int b_col = (tid & 31) << 2;    // 0..124

    const float* Aptr = A + (size_t)(bm + a_row) * K + a_col;
    const float* Bptr = B + (size_t)b_row * N + bn + b_col;

    float acc[8][8];
#pragma unroll
    for (int i = 0; i < 8; i++)
#pragma unroll
        for (int j = 0; j < 8; j++) acc[i][j] = 0.f;

    float4 av = *(const float4*)Aptr;
    float4 bv = *(const float4*)Bptr;

    for (int k0 = 0; k0 < K; k0 += 8) {
        As[a_col + 0][a_row] = av.x;
        As[a_col + 1][a_row] = av.y;
        As[a_col + 2][a_row] = av.z;
        As[a_col + 3][a_row] = av.w;
        *(float4*)&Bs[b_row][b_col] = bv;
        __syncthreads();

        if (k0 + 8 < K) {
            av = *(const float4*)(Aptr + k0 + 8);
            bv = *(const float4*)(Bptr + (size_t)(k0 + 8) * N);
        }

#pragma unroll
        for (int kk = 0; kk < 8; kk++) {
            float4 raA = *(const float4*)&As[kk][ty * 8];
            float4 raB = *(const float4*)&As[kk][ty * 8 + 4];
            float4 rbA = *(const float4*)&Bs[kk][tx * 8];
            float4 rbB = *(const float4*)&Bs[kk][tx * 8 + 4];
            float ra[8] = {raA.x, raA.y, raA.z, raA.w, raB.x, raB.y, raB.z, raB.w};
            float rb[8] = {rbA.x, rbA.y, rbA.z, rbA.w, rbB.x, rbB.y, rbB.z, rbB.w};
#pragma unroll
            for (int i = 0; i < 8; i++)
#pragma unroll
                for (int j = 0; j < 8; j++)
                    acc[i][j] = fmaf(ra[i], rb[j], acc[i][j]);
        }
        __syncthreads();
    }

#pragma unroll
    for (int i = 0; i < 8; i++) {
        int m = bm + ty * 8 + i;
        int n0 = bn + tx * 8;
        float* dst;
        if (mode == 0) {
            dst = C + (size_t)m * N + n0;
        } else {
            int b  = m >> 11;         // m / 2048
            int s  = m & 2047;
            int h  = n0 >> 8;         // n0 / 256 (tile never crosses head)
            int hd = n0 & 255;
            dst = C + (((size_t)(b * NH + h) * SEQ + s) * HDIM) + hd;
        }
        *(float4*)(dst)     = make_float4(acc[i][0], acc[i][1], acc[i][2], acc[i][3]);
        *(float4*)(dst + 4) = make_float4(acc[i][4], acc[i][5], acc[i][6], acc[i][7]);
    }
}

// ---------------------------------------------------------------------------
// RoPE (GPT-J interleaved) on first ROTD dims of Q and K ([B,H,S,HD]).
// One thread per (b,h,s,pair). Angles in double for robust reduction.
// ---------------------------------------------------------------------------
__global__ void rope_kernel(float* __restrict__ Q, float* __restrict__ K,
                            const int* __restrict__ pos)
{
    int idx = blockIdx.x * blockDim.x + threadIdx.x;
    const int total = MB * NH * SEQ * (ROTD / 2);
    if (idx >= total) return;
    int i  = idx & 31;            // pair index 0..31
    int s  = (idx >> 5) & (SEQ - 1);
    int bh = idx >> 16;           // 0..31
    int b  = bh >> 4;

    int p = pos[b * SEQ + s];
    double inv = pow(10000.0, -(double)(2 * i) / (double)ROTD);
    double ang = (double)p * inv;
    float sn = (float)sin(ang);
    float cs = (float)cos(ang);

    size_t base = ((size_t)bh * SEQ + s) * HDIM + 2 * i;
    float q0 = Q[base], q1 = Q[base + 1];
    Q[base]     = q0 * cs - q1 * sn;
    Q[base + 1] = q1 * cs + q0 * sn;
    float k0 = K[base], k1 = K[base + 1];
    K[base]     = k0 * cs - k1 * sn;
    K[base + 1] = k1 * cs + k0 * sn;
}

// ---------------------------------------------------------------------------
// Causal flash attention, fp32, online softmax.
// Block: (q-tile of 32, bh). 256 threads: thread = (row r 0..31, dim-group g 0..7),
// owns dims [g*32, g*32+32). K/V tiles (32x256 each) in smem, XOR-swizzled so
// that the 128B-strided per-g column reads are bank-conflict-free.
// Scores: per-thread partial over 32 dims, 8-lane shfl_xor reduction.
// ---------------------------------------------------------------------------
__device__ __forceinline__ int swz(int col, int gsw) { return col ^ gsw; }

__global__ void attn_kernel(const float* __restrict__ Q, const float* __restrict__ K,
                            const float* __restrict__ V, float* __restrict__ CTX)
{
    extern __shared__ float sm[];
    float* Ks = sm;                 // 32 * 256
    float* Vs = sm + 32 * HDIM;     // 32 * 256

    int qt  = blockIdx.x;           // 0..63
    int bh  = blockIdx.y;           // 0..31
    int b   = bh >> 4, h = bh & 15;
    int tid = threadIdx.x;
    int r   = tid >> 3;             // 0..31
    int g   = tid & 7;              // 0..7
    int gsw = g << 2;
    int s_q = qt * 32 + r;

    const float* qp = Q + ((size_t)bh * SEQ + s_q) * HDIM + g * 32;
    float q[32], o[32];
#pragma unroll
    for (int c = 0; c < 8; c++) {
        float4 t = *(const float4*)(qp + c * 4);
        q[c * 4 + 0] = t.x; q[c * 4 + 1] = t.y;
        q[c * 4 + 2] = t.z; q[c * 4 + 3] = t.w;
    }
#pragma unroll
    for (int i = 0; i < 32; i++) o[i] = 0.f;
    float m_run = -1e30f, l_run = 0.f;

    for (int kt = 0; kt <= qt; kt++) {
        const float* kp = K + ((size_t)bh * SEQ + kt * 32 + r) * HDIM + g * 32;
        const float* vp = V + ((size_t)bh * SEQ + kt * 32 + r) * HDIM + g * 32;
        __syncthreads();   // previous tile fully consumed
#pragma unroll
        for (int c = 0; c < 8; c++) {
            int sc = swz(g * 32 + c * 4, gsw);
            *(float4*)&Ks[r * HDIM + sc] = *(const float4*)(kp + c * 4);
            *(float4*)&Vs[r * HDIM + sc] = *(const float4*)(vp + c * 4);
        }
        __syncthreads();

        // partial scores over this thread's 32 dims, for all 32 keys
        float p[32];
#pragma unroll
        for (int j = 0; j < 32; j++) p[j] = 0.f;
#pragma unroll
        for (int c = 0; c < 8; c++) {
            float qx = q[c * 4 + 0], qy = q[c * 4 + 1];
            float qz = q[c * 4 + 2], qw = q[c * 4 + 3];
            int sc = swz(g * 32 + c * 4, gsw);
#pragma unroll
            for (int j = 0; j < 32; j++) {
                float4 kv = *(const float4*)&Ks[j * HDIM + sc];
                p[j] = fmaf(qx, kv.x, p[j]);
                p[j] = fmaf(qy, kv.y, p[j]);
                p[j] = fmaf(qz, kv.z, p[j]);
                p[j] = fmaf(qw, kv.w, p[j]);
            }
        }
        // reduce across the 8 lanes of this row (lanes r*8 .. r*8+7, same warp)
#pragma unroll
        for (int j = 0; j < 32; j++) {
            p[j] += __shfl_xor_sync(0xffffffffu, p[j], 1);
            p[j] += __shfl_xor_sync(0xffffffffu, p[j], 2);
            p[j] += __shfl_xor_sync(0xffffffffu, p[j], 4);
        }

        int kbase = kt * 32;
        float mt = m_run;
#pragma unroll
        for (int j = 0; j < 32; j++) {
            float scv = p[j] * 0.0625f;           // 1/sqrt(256)
            if (kbase + j > s_q) scv = -1e30f;    // causal mask
            p[j] = scv;
            mt = fmaxf(mt, scv);
        }
        float alpha = __expf(m_run - mt);
        float lsum = 0.f;
#pragma unroll
        for (int j = 0; j < 32; j++) {
            p[j] = __expf(p[j] - mt);
            lsum += p[j];
        }
        l_run = l_run * alpha + lsum;
        m_run = mt;
#pragma unroll
        for (int i = 0; i < 32; i++) o[i] *= alpha;

        // o += P @ V over this thread's 32 dims
#pragma unroll
        for (int j = 0; j < 32; j++) {
            float e = p[j];
#pragma unroll
            for (int c = 0; c < 8; c++) {
                int sc = swz(g * 32 + c * 4, gsw);
                float4 vv = *(const float4*)&Vs[j * HDIM + sc];
                o[c * 4 + 0] = fmaf(e, vv.x, o[c * 4 + 0]);
                o[c * 4 + 1] = fmaf(e, vv.y, o[c * 4 + 1]);
                o[c * 4 + 2] = fmaf(e, vv.z, o[c * 4 + 2]);
                o[c * 4 + 3] = fmaf(e, vv.w, o[c * 4 + 3]);
            }
        }
    }

    float inv_l = 1.0f / l_run;
    // write CTX in [B,S,D] layout so the output GEMM reads plain row-major
    float* op = CTX + ((size_t)(b * SEQ + s_q)) * DM + h * HDIM + g * 32;
#pragma unroll
    for (int c = 0; c < 8; c++)
        *(float4*)(op + c * 4) = make_float4(o[c * 4 + 0] * inv_l, o[c * 4 + 1] * inv_l,
                                             o[c * 4 + 2] * inv_l, o[c * 4 + 3] * inv_l);
}

// ---------------------------------------------------------------------------
extern "C" void kernel_launch(void* const* d_in, const int* in_sizes, int n_in,
                              void* d_out, int out_size)
{
    const float* X   = (const float*)d_in[0];
    const int*   pos = (const int*)  d_in[1];
    const float* Wq  = (const float*)d_in[2];
    const float* Wk  = (const float*)d_in[3];
    const float* Wv  = (const float*)d_in[4];
    const float* Wo  = (const float*)d_in[5];
    float* out = (float*)d_out;

    float *Qg, *Kg, *Vg, *CTX;
    cudaGetSymbolAddress((void**)&Qg,  g_Q);
    cudaGetSymbolAddress((void**)&Kg,  g_K);
    cudaGetSymbolAddress((void**)&Vg,  g_V);
    cudaGetSymbolAddress((void**)&CTX, g_CTX);

    dim3 gg(DM / 128, DM / 128);   // 32 x 32
    sgemm_kernel<<<gg, 256>>>(X, Wq, Qg, 1);
    sgemm_kernel<<<gg, 256>>>(X, Wk, Kg, 1);
    sgemm_kernel<<<gg, 256>>>(X, Wv, Vg, 1);

    int rt = MB * NH * SEQ * (ROTD / 2);
    rope_kernel<<<(rt + 255) / 256, 256>>>(Qg, Kg, pos);

    cudaFuncSetAttribute(attn_kernel, cudaFuncAttributeMaxDynamicSharedMemorySize, 65536);
    attn_kernel<<<dim3(SEQ / 32, MB * NH), 256, 65536>>>(Qg, Kg, Vg, CTX);

    sgemm_kernel<<<gg, 256>>>(CTX, Wo, out, 0);
}

// round 3
// speedup vs baseline: 1.8432x; 1.8432x over previous
#include <cuda_runtime.h>
#include <cuda_bf16.h>
#include <stdint.h>
#include <math.h>

#define MB   2
#define SEQ  2048
#define DM   4096
#define NH   16
#define HDIM 256
#define ROTD 64

#define BM 128
#define BN 128
#define BK 64
#define NKT (DM / BK)       // 64 K-chunks
#define BLK_BYTES 16384     // one 128x64 bf16 tile, SW128-swizzled image

// ---------------- scratch ----------------
__device__ float g_Q[(size_t)MB * NH * SEQ * HDIM];
__device__ float g_K[(size_t)MB * NH * SEQ * HDIM];
__device__ float g_V[(size_t)MB * NH * SEQ * HDIM];
__device__ float g_CTX[(size_t)MB * SEQ * DM];

// tiled + swizzled bf16 operand images: blocks (rt, kt) of 128x64, 16KB each
__device__ __align__(1024) __nv_bfloat16 g_Xhi[(size_t)DM * DM];
__device__ __align__(1024) __nv_bfloat16 g_Xlo[(size_t)DM * DM];
__device__ __align__(1024) __nv_bfloat16 g_Chi[(size_t)DM * DM];
__device__ __align__(1024) __nv_bfloat16 g_Clo[(size_t)DM * DM];
__device__ __align__(1024) __nv_bfloat16 g_WThi[4][(size_t)DM * DM];
__device__ __align__(1024) __nv_bfloat16 g_WTlo[4][(size_t)DM * DM];

// ---------------- helpers ----------------
__device__ __forceinline__ uint32_t smem_to_u32(const void* p) {
    uint32_t a;
    asm("{ .reg .u64 t; cvta.to.shared.u64 t, %1; cvt.u32.u64 %0, t; }" : "=r"(a) : "l"(p));
    return a;
}
#define MBARRIER_INIT(a, c) \
    asm volatile("mbarrier.init.shared.b64 [%0], %1;" :: "r"((uint32_t)(a)), "r"((uint32_t)(c)) : "memory")
#define MBARRIER_EXPECT_TX(a, tx) \
    asm volatile("mbarrier.arrive.expect_tx.shared.b64 _, [%0], %1;" :: "r"((uint32_t)(a)), "r"((uint32_t)(tx)) : "memory")
#define FENCE_PROXY_ASYNC() asm volatile("fence.proxy.async.shared::cta;" ::: "memory")
#define MBARRIER_WAIT_PARITY(mbar_smem_addr, phase_parity) do { \
    uint32_t _mbar = (uint32_t)(mbar_smem_addr); \
    uint32_t _parity = (uint32_t)(phase_parity); \
    uint32_t _done; \
    asm volatile("{\n\t.reg .pred p;\n\t" \
        "mbarrier.try_wait.parity.acquire.cta.shared::cta.b64 p, [%1], %2;\n\t" \
        "selp.b32 %0, 1, 0, p;\n\t}" \
        : "=r"(_done) : "r"(_mbar), "r"(_parity) : "memory"); \
    if (!_done) { \
        asm volatile("{\n\t.reg .pred P1;\n\t" \
            "WAIT_LOOP_%=:\n\t" \
            "mbarrier.try_wait.parity.acquire.cta.shared::cta.b64 P1, [%0], %1, 0x989680;\n\t" \
            "@P1 bra.uni WAIT_DONE_%=;\n\t" \
            "bra.uni WAIT_LOOP_%=;\n\t" \
            "WAIT_DONE_%=:\n\t}" \
            :: "r"(_mbar), "r"(_parity) : "memory"); \
    } \
} while(0)

__device__ __forceinline__ void tma_bulk(uint32_t dst, const void* src, uint32_t bytes, uint32_t mbar) {
    asm volatile("cp.async.bulk.shared::cluster.global.mbarrier::complete_tx::bytes [%0], [%1], %2, [%3];"
        :: "r"(dst), "l"(src), "r"(bytes), "r"(mbar) : "memory");
}

#define SMEM_SWIZZLE_128B(x) ((x) ^ (((x) >> 3) & 0x70))

#define LDSM4(r, addr) \
    asm volatile("ldmatrix.sync.aligned.m8n8.x4.shared.b16 {%0,%1,%2,%3}, [%4];" \
        : "=r"((r)[0]), "=r"((r)[1]), "=r"((r)[2]), "=r"((r)[3]) : "r"(addr))

__device__ __forceinline__ void mma16816(float* c, const uint32_t* a, uint32_t b0, uint32_t b1) {
    asm volatile("mma.sync.aligned.m16n8k16.row.col.f32.bf16.bf16.f32 "
        "{%0,%1,%2,%3}, {%4,%5,%6,%7}, {%8,%9}, {%0,%1,%2,%3};"
        : "+f"(c[0]), "+f"(c[1]), "+f"(c[2]), "+f"(c[3])
        : "r"(a[0]), "r"(a[1]), "r"(a[2]), "r"(a[3]), "r"(b0), "r"(b1));
}

__device__ __forceinline__ void split1(float v, __nv_bfloat16& h, __nv_bfloat16& l) {
    h = __float2bfloat16(v);
    l = __float2bfloat16(v - __bfloat162float(h));
}

// ---------------------------------------------------------------------------
// split fp32 row-major [4096][4096] -> tiled+swizzled bf16 hi/lo blocks
// one thread per 8 consecutive K elements (one 16B swizzle chunk)
// ---------------------------------------------------------------------------
__global__ void __launch_bounds__(256) split_rm_tiled(const float* __restrict__ in,
                                                      __nv_bfloat16* __restrict__ hi,
                                                      __nv_bfloat16* __restrict__ lo)
{
    size_t idx = (size_t)blockIdx.x * 256 + threadIdx.x;   // 2,097,152 total
    int m  = (int)(idx >> 9);
    int k  = (int)(idx & 511) << 3;
    const float4* p = (const float4*)(in + ((size_t)m << 12) + k);
    float4 v0 = p[0], v1 = p[1];

    __nv_bfloat16 h[8], l[8];
    split1(v0.x, h[0], l[0]); split1(v0.y, h[1], l[1]);
    split1(v0.z, h[2], l[2]); split1(v0.w, h[3], l[3]);
    split1(v1.x, h[4], l[4]); split1(v1.y, h[5], l[5]);
    split1(v1.z, h[6], l[6]); split1(v1.w, h[7], l[7]);

    int mt = m >> 7, r = m & 127, kt = k >> 6, c = k & 63;
    size_t base = ((size_t)mt * NKT + kt) * BLK_BYTES
                + SMEM_SWIZZLE_128B((uint32_t)(r * 128 + c * 2));
    *(uint4*)((char*)hi + base) = *(uint4*)h;
    *(uint4*)((char*)lo + base) = *(uint4*)l;
}

// ---------------------------------------------------------------------------
// W [K][N] fp32 -> BT tiled+swizzled bf16 hi/lo (transpose + split)
// 32x32 tile per block, 256 threads
// ---------------------------------------------------------------------------
__global__ void __launch_bounds__(256) split_tr_tiled(const float* __restrict__ W,
                                                      __nv_bfloat16* __restrict__ Thi,
                                                      __nv_bfloat16* __restrict__ Tlo)
{
    __shared__ float t[32][33];
    int w = threadIdx.x;
    int nb = blockIdx.x * 32, kb = blockIdx.y * 32;
    int tx = w & 31, ty = w >> 5;                  // 32 x 8
#pragma unroll
    for (int j = 0; j < 4; j++)
        t[ty + j * 8][tx] = W[(size_t)(kb + ty + j * 8) * DM + nb + tx];
    __syncthreads();

    int half = w >> 7, w7 = w & 127;
    int nn = w7 >> 2, kc = (w7 & 3) * 8;
    int n = nb + nn, kk = kb + kc;
    float v[8];
#pragma unroll
    for (int q = 0; q < 8; q++) v[q] = t[kc + q][nn];

    int nt = n >> 7, r = n & 127, kt = kk >> 6, c = kk & 63;
    size_t base = ((size_t)nt * NKT + kt) * BLK_BYTES
                + SMEM_SWIZZLE_128B((uint32_t)(r * 128 + c * 2));
    __nv_bfloat16 o[8];
    if (half == 0) {
#pragma unroll
        for (int q = 0; q < 8; q++) o[q] = __float2bfloat16(v[q]);
        *(uint4*)((char*)Thi + base) = *(uint4*)o;
    } else {
#pragma unroll
        for (int q = 0; q < 8; q++) {
            __nv_bfloat16 hh = __float2bfloat16(v[q]);
            o[q] = __float2bfloat16(v[q] - __bfloat162float(hh));
        }
        *(uint4*)((char*)Tlo + base) = *(uint4*)o;
    }
}

// ---------------------------------------------------------------------------
// HMMA split-bf16 GEMM: C[M,N] = A @ BT^T.
// A,B prepacked tiled+swizzled. cp.async.bulk double-buffered, mma.sync.
// mode 0: C row-major [4096][4096]; mode 1: scatter to [B,H,S,HD].
// ---------------------------------------------------------------------------
__global__ void __launch_bounds__(256, 1) gemm_hmma(
    const __nv_bfloat16* __restrict__ Ahi, const __nv_bfloat16* __restrict__ Alo,
    const __nv_bfloat16* __restrict__ Bhi, const __nv_bfloat16* __restrict__ Blo,
    float* __restrict__ C, int mode)
{
    extern __shared__ char gsm[];
    uint32_t sb = (smem_to_u32(gsm) + 1023u) & ~1023u;   // 1024-aligned
    const uint32_t stage0 = sb + 1024u;                   // 2 stages x 64KB
    const int tid = threadIdx.x, wid = tid >> 5, lane = tid & 31;
    const int bm = blockIdx.y * BM, bn = blockIdx.x * BN;
    const int wm = wid >> 2, wn = wid & 3;                // warp grid 2(M) x 4(N)

    if (tid == 0) {
        MBARRIER_INIT(sb, 1);
        MBARRIER_INIT(sb + 8, 1);
        FENCE_PROXY_ASYNC();
    }
    __syncthreads();

    const char* pAh = (const char*)Ahi + ((size_t)blockIdx.y << 20);
    const char* pAl = (const char*)Alo + ((size_t)blockIdx.y << 20);
    const char* pBh = (const char*)Bhi + ((size_t)blockIdx.x << 20);
    const char* pBl = (const char*)Blo + ((size_t)blockIdx.x << 20);

    auto issue = [&](int i) {
        const int s = i & 1;
        const uint32_t st = stage0 + (uint32_t)s * 65536u;
        const uint32_t mb = sb + (uint32_t)s * 8u;
        const size_t off = (size_t)i << 14;
        MBARRIER_EXPECT_TX(mb, 65536u);
        tma_bulk(st,           pAh + off, 16384u, mb);
        tma_bulk(st + 16384u,  pAl + off, 16384u, mb);
        tma_bulk(st + 32768u,  pBh + off, 16384u, mb);
        tma_bulk(st + 49152u,  pBl + off, 16384u, mb);
    };
    if (tid == 0) { issue(0); issue(1); }

    float acc[16][4];
#pragma unroll
    for (int i = 0; i < 16; i++)
#pragma unroll
        for (int j = 0; j < 4; j++) acc[i][j] = 0.f;

    const int ra = lane & 15, ca = (lane >> 4) * 16;              // A ldmatrix lane map
    const int rb = (lane & 7) + 8 * ((lane >> 3) & 1), cb = (lane >> 4) * 16;  // B

    int ph0 = 0, ph1 = 0;
    for (int i = 0; i < NKT; i++) {
        const int s = i & 1;
        const uint32_t st = stage0 + (uint32_t)s * 65536u;
        if (s == 0) { MBARRIER_WAIT_PARITY(sb, ph0);     ph0 ^= 1; }
        else        { MBARRIER_WAIT_PARITY(sb + 8, ph1); ph1 ^= 1; }

#pragma unroll
        for (int ks = 0; ks < 4; ks++) {
            uint32_t ah[4][4], al[4][4], bh[2][4], bl[2][4];
#pragma unroll
            for (int im = 0; im < 4; im++) {
                uint32_t off = SMEM_SWIZZLE_128B(
                    (uint32_t)((wm * 64 + im * 16 + ra) * 128 + ks * 32 + ca));
                LDSM4(ah[im], st + off);
                LDSM4(al[im], st + 16384u + off);
            }
#pragma unroll
            for (int ip = 0; ip < 2; ip++) {
                uint32_t off = SMEM_SWIZZLE_128B(
                    (uint32_t)((wn * 32 + ip * 16 + rb) * 128 + ks * 32 + cb));
                LDSM4(bh[ip], st + 32768u + off);
                LDSM4(bl[ip], st + 49152u + off);
            }
#pragma unroll
            for (int im = 0; im < 4; im++)
#pragma unroll
                for (int in = 0; in < 4; in++) {
                    const int ip = in >> 1, sel = in & 1;
                    float* c = acc[im * 4 + in];
                    mma16816(c, ah[im], bh[ip][sel], bh[ip][sel + 2]);
                    mma16816(c, ah[im], bl[ip][sel], bl[ip][sel + 2]);
                    mma16816(c, al[im], bh[ip][sel], bh[ip][sel + 2]);
                }
        }
        __syncthreads();
        if (tid == 0 && i + 2 < NKT) issue(i + 2);
    }

    // epilogue: acc[im*4+in] -> rows bm+wm*64+im*16+{lane>>2, +8}, cols bn+wn*32+in*8+(lane&3)*2
#pragma unroll
    for (int im = 0; im < 4; im++) {
#pragma unroll
        for (int in = 0; in < 4; in++) {
            const float* c = acc[im * 4 + in];
            int m0 = bm + wm * 64 + im * 16 + (lane >> 2);
            int n  = bn + wn * 32 + in * 8 + (lane & 3) * 2;
#pragma unroll
            for (int half = 0; half < 2; half++) {
                int m = m0 + half * 8;
                float2 v = half ? make_float2(c[2], c[3]) : make_float2(c[0], c[1]);
                if (mode == 0) {
                    *(float2*)(C + (size_t)m * DM + n) = v;
                } else {
                    int b = m >> 11, sq = m & 2047, h = n >> 8, hd = n & 255;
                    *(float2*)(C + ((size_t)(b * NH + h) * SEQ + sq) * HDIM + hd) = v;
                }
            }
        }
    }
}

// ---------------------------------------------------------------------------
// RoPE (GPT-J interleaved). One thread per (s, pair); loops over b, h.
// ---------------------------------------------------------------------------
__global__ void __launch_bounds__(256) rope_kernel(float* __restrict__ Q, float* __restrict__ K,
                                                   const int* __restrict__ pos)
{
    int idx = blockIdx.x * blockDim.x + threadIdx.x;
    if (idx >= SEQ * 32) return;
    int i = idx & 31, s = idx >> 5;
    double inv = pow(10000.0, -(double)(2 * i) / (double)ROTD);
#pragma unroll
    for (int b = 0; b < MB; b++) {
        int p = pos[b * SEQ + s];
        double sn_, cs_;
        sincos((double)p * inv, &sn_, &cs_);
        float sn = (float)sn_, cs = (float)cs_;
#pragma unroll
        for (int h = 0; h < NH; h++) {
            size_t base = ((size_t)(b * NH + h) * SEQ + s) * HDIM + 2 * i;
            float2 q = *(float2*)(Q + base);
            *(float2*)(Q + base) = make_float2(q.x * cs - q.y * sn, q.y * cs + q.x * sn);
            float2 k = *(float2*)(K + base);
            *(float2*)(K + base) = make_float2(k.x * cs - k.y * sn, k.y * cs + k.x * sn);
        }
    }
}

// ---------------------------------------------------------------------------
// Causal flash attention, fp32, online softmax (validated round 1).
// ---------------------------------------------------------------------------
__device__ __forceinline__ int swz(int col, int gsw) { return col ^ gsw; }

__global__ void attn_kernel(const float* __restrict__ Q, const float* __restrict__ K,
                            const float* __restrict__ V, float* __restrict__ CTX)
{
    extern __shared__ float sm[];
    float* Ks = sm;
    float* Vs = sm + 32 * HDIM;

    int qt  = blockIdx.x;
    int bh  = blockIdx.y;
    int b   = bh >> 4, h = bh & 15;
    int tid = threadIdx.x;
    int r   = tid >> 3;
    int g   = tid & 7;
    int gsw = g << 2;
    int s_q = qt * 32 + r;

    const float* qp = Q + ((size_t)bh * SEQ + s_q) * HDIM + g * 32;
    float q[32], o[32];
#pragma unroll
    for (int c = 0; c < 8; c++) {
        float4 t = *(const float4*)(qp + c * 4);
        q[c * 4 + 0] = t.x; q[c * 4 + 1] = t.y;
        q[c * 4 + 2] = t.z; q[c * 4 + 3] = t.w;
    }
#pragma unroll
    for (int i = 0; i < 32; i++) o[i] = 0.f;
    float m_run = -1e30f, l_run = 0.f;

    for (int kt = 0; kt <= qt; kt++) {
        const float* kp = K + ((size_t)bh * SEQ + kt * 32 + r) * HDIM + g * 32;
        const float* vp = V + ((size_t)bh * SEQ + kt * 32 + r) * HDIM + g * 32;
        __syncthreads();
#pragma unroll
        for (int c = 0; c < 8; c++) {
            int sc = swz(g * 32 + c * 4, gsw);
            *(float4*)&Ks[r * HDIM + sc] = *(const float4*)(kp + c * 4);
            *(float4*)&Vs[r * HDIM + sc] = *(const float4*)(vp + c * 4);
        }
        __syncthreads();

        float p[32];
#pragma unroll
        for (int j = 0; j < 32; j++) p[j] = 0.f;
#pragma unroll
        for (int c = 0; c < 8; c++) {
            float qx = q[c * 4 + 0], qy = q[c * 4 + 1];
            float qz = q[c * 4 + 2], qw = q[c * 4 + 3];
            int sc = swz(g * 32 + c * 4, gsw);
#pragma unroll
            for (int j = 0; j < 32; j++) {
                float4 kv = *(const float4*)&Ks[j * HDIM + sc];
                p[j] = fmaf(qx, kv.x, p[j]);
                p[j] = fmaf(qy, kv.y, p[j]);
                p[j] = fmaf(qz, kv.z, p[j]);
                p[j] = fmaf(qw, kv.w, p[j]);
            }
        }
#pragma unroll
        for (int j = 0; j < 32; j++) {
            p[j] += __shfl_xor_sync(0xffffffffu, p[j], 1);
            p[j] += __shfl_xor_sync(0xffffffffu, p[j], 2);
            p[j] += __shfl_xor_sync(0xffffffffu, p[j], 4);
        }

        int kbase = kt * 32;
        float mt = m_run;
#pragma unroll
        for (int j = 0; j < 32; j++) {
            float scv = p[j] * 0.0625f;
            if (kbase + j > s_q) scv = -1e30f;
            p[j] = scv;
            mt = fmaxf(mt, scv);
        }
        float alpha = __expf(m_run - mt);
        float lsum = 0.f;
#pragma unroll
        for (int j = 0; j < 32; j++) {
            p[j] = __expf(p[j] - mt);
            lsum += p[j];
        }
        l_run = l_run * alpha + lsum;
        m_run = mt;
#pragma unroll
        for (int i = 0; i < 32; i++) o[i] *= alpha;

#pragma unroll
        for (int j = 0; j < 32; j++) {
            float e = p[j];
#pragma unroll
            for (int c = 0; c < 8; c++) {
                int sc = swz(g * 32 + c * 4, gsw);
                float4 vv = *(const float4*)&Vs[j * HDIM + sc];
                o[c * 4 + 0] = fmaf(e, vv.x, o[c * 4 + 0]);
                o[c * 4 + 1] = fmaf(e, vv.y, o[c * 4 + 1]);
                o[c * 4 + 2] = fmaf(e, vv.z, o[c * 4 + 2]);
                o[c * 4 + 3] = fmaf(e, vv.w, o[c * 4 + 3]);
            }
        }
    }

    float inv_l = 1.0f / l_run;
    float* op = CTX + ((size_t)(b * SEQ + s_q)) * DM + h * HDIM + g * 32;
#pragma unroll
    for (int c = 0; c < 8; c++)
        *(float4*)(op + c * 4) = make_float4(o[c * 4 + 0] * inv_l, o[c * 4 + 1] * inv_l,
                                             o[c * 4 + 2] * inv_l, o[c * 4 + 3] * inv_l);
}

// ---------------------------------------------------------------------------
extern "C" void kernel_launch(void* const* d_in, const int* in_sizes, int n_in,
                              void* d_out, int out_size)
{
    const float* X   = (const float*)d_in[0];
    const int*   pos = (const int*)  d_in[1];
    const float* W[4] = { (const float*)d_in[2], (const float*)d_in[3],
                          (const float*)d_in[4], (const float*)d_in[5] };
    float* out = (float*)d_out;

    float *Qg, *Kg, *Vg, *CTX;
    __nv_bfloat16 *Xhi, *Xlo, *Chi, *Clo, *WThi, *WTlo;
    cudaGetSymbolAddress((void**)&Qg,  g_Q);
    cudaGetSymbolAddress((void**)&Kg,  g_K);
    cudaGetSymbolAddress((void**)&Vg,  g_V);
    cudaGetSymbolAddress((void**)&CTX, g_CTX);
    cudaGetSymbolAddress((void**)&Xhi, g_Xhi);
    cudaGetSymbolAddress((void**)&Xlo, g_Xlo);
    cudaGetSymbolAddress((void**)&Chi, g_Chi);
    cudaGetSymbolAddress((void**)&Clo, g_Clo);
    cudaGetSymbolAddress((void**)&WThi, g_WThi);
    cudaGetSymbolAddress((void**)&WTlo, g_WTlo);

    const int GEMM_SMEM = 1024 + 1024 + 2 * 65536;   // align slack + barriers + stages
    cudaFuncSetAttribute(gemm_hmma, cudaFuncAttributeMaxDynamicSharedMemorySize, GEMM_SMEM);
    cudaFuncSetAttribute(attn_kernel, cudaFuncAttributeMaxDynamicSharedMemorySize, 65536);

    const size_t WSZ = (size_t)DM * DM;
    dim3 trg(DM / 32, DM / 32);
    dim3 gg(DM / BN, DM / BM);   // 32 x 32

    // pack operands
    split_rm_tiled<<<8192, 256>>>(X, Xhi, Xlo);
    for (int w = 0; w < 4; w++)
        split_tr_tiled<<<trg, 256>>>(W[w], WThi + (size_t)w * WSZ, WTlo + (size_t)w * WSZ);

    // QKV projections (scatter to [B,H,S,HD])
    gemm_hmma<<<gg, 256, GEMM_SMEM>>>(Xhi, Xlo, WThi + 0 * WSZ, WTlo + 0 * WSZ, Qg, 1);
    gemm_hmma<<<gg, 256, GEMM_SMEM>>>(Xhi, Xlo, WThi + 1 * WSZ, WTlo + 1 * WSZ, Kg, 1);
    gemm_hmma<<<gg, 256, GEMM_SMEM>>>(Xhi, Xlo, WThi + 2 * WSZ, WTlo + 2 * WSZ, Vg, 1);

    rope_kernel<<<(SEQ * 32 + 255) / 256, 256>>>(Qg, Kg, pos);

    attn_kernel<<<dim3(SEQ / 32, MB * NH), 256, 65536>>>(Qg, Kg, Vg, CTX);

    // output projection
    split_rm_tiled<<<8192, 256>>>(CTX, Chi, Clo);
    gemm_hmma<<<gg, 256, GEMM_SMEM>>>(Chi, Clo, WThi + 3 * WSZ, WTlo + 3 * WSZ, out, 0);
}

// round 4
// speedup vs baseline: 3.4588x; 1.8765x over previous
#include <cuda_runtime.h>
#include <cuda_bf16.h>
#include <stdint.h>
#include <math.h>

#define MB   2
#define SEQ  2048
#define DM   4096
#define NH   16
#define HDIM 256
#define ROTD 64

#define BM 128
#define BN 128
#define BK 64
#define NKT (DM / BK)       // 64 K-chunks
#define BLK_BYTES 16384     // one 128x64 bf16 tile, SW128-swizzled image

// ---------------- scratch ----------------
__device__ float g_Q[(size_t)MB * NH * SEQ * HDIM];
__device__ float g_K[(size_t)MB * NH * SEQ * HDIM];
__device__ float g_V[(size_t)MB * NH * SEQ * HDIM];
__device__ float g_CTX[(size_t)MB * SEQ * DM];

// tiled + swizzled bf16 operand images for GEMMs
__device__ __align__(1024) __nv_bfloat16 g_Xhi[(size_t)DM * DM];
__device__ __align__(1024) __nv_bfloat16 g_Xlo[(size_t)DM * DM];
__device__ __align__(1024) __nv_bfloat16 g_Chi[(size_t)DM * DM];
__device__ __align__(1024) __nv_bfloat16 g_Clo[(size_t)DM * DM];
__device__ __align__(1024) __nv_bfloat16 g_WThi[4][(size_t)DM * DM];
__device__ __align__(1024) __nv_bfloat16 g_WTlo[4][(size_t)DM * DM];

// attention packed operands
// Q/K: [bh 32][st 64][ct 4][32 rows][64 cols] 4KB blocks, SW128
// V:   [bh 32][jt 64][dt 2][128 rows(d)][32 cols(j)] 8KB blocks, swz64
__device__ __align__(1024) __nv_bfloat16 g_Qph[(size_t)32 * 2048 * 256];
__device__ __align__(1024) __nv_bfloat16 g_Qpl[(size_t)32 * 2048 * 256];
__device__ __align__(1024) __nv_bfloat16 g_Kph[(size_t)32 * 2048 * 256];
__device__ __align__(1024) __nv_bfloat16 g_Kpl[(size_t)32 * 2048 * 256];
__device__ __align__(1024) __nv_bfloat16 g_Vph[(size_t)32 * 2048 * 256];
__device__ __align__(1024) __nv_bfloat16 g_Vpl[(size_t)32 * 2048 * 256];

// ---------------- helpers ----------------
__device__ __forceinline__ uint32_t smem_to_u32(const void* p) {
    uint32_t a;
    asm("{ .reg .u64 t; cvta.to.shared.u64 t, %1; cvt.u32.u64 %0, t; }" : "=r"(a) : "l"(p));
    return a;
}
#define MBARRIER_INIT(a, c) \
    asm volatile("mbarrier.init.shared.b64 [%0], %1;" :: "r"((uint32_t)(a)), "r"((uint32_t)(c)) : "memory")
#define MBARRIER_EXPECT_TX(a, tx) \
    asm volatile("mbarrier.arrive.expect_tx.shared.b64 _, [%0], %1;" :: "r"((uint32_t)(a)), "r"((uint32_t)(tx)) : "memory")
#define MBARRIER_ARRIVE(a) \
    asm volatile("mbarrier.arrive.shared.b64 _, [%0];" :: "r"((uint32_t)(a)) : "memory")
#define FENCE_PROXY_ASYNC() asm volatile("fence.proxy.async.shared::cta;" ::: "memory")
#define MBARRIER_WAIT_PARITY(mbar_smem_addr, phase_parity) do { \
    uint32_t _mbar = (uint32_t)(mbar_smem_addr); \
    uint32_t _parity = (uint32_t)(phase_parity); \
    uint32_t _done; \
    asm volatile("{\n\t.reg .pred p;\n\t" \
        "mbarrier.try_wait.parity.acquire.cta.shared::cta.b64 p, [%1], %2;\n\t" \
        "selp.b32 %0, 1, 0, p;\n\t}" \
        : "=r"(_done) : "r"(_mbar), "r"(_parity) : "memory"); \
    if (!_done) { \
        asm volatile("{\n\t.reg .pred P1;\n\t" \
            "WAIT_LOOP_%=:\n\t" \
            "mbarrier.try_wait.parity.acquire.cta.shared::cta.b64 P1, [%0], %1, 0x989680;\n\t" \
            "@P1 bra.uni WAIT_DONE_%=;\n\t" \
            "bra.uni WAIT_LOOP_%=;\n\t" \
            "WAIT_DONE_%=:\n\t}" \
            :: "r"(_mbar), "r"(_parity) : "memory"); \
    } \
} while(0)

__device__ __forceinline__ void tma_bulk(uint32_t dst, const void* src, uint32_t bytes, uint32_t mbar) {
    asm volatile("cp.async.bulk.shared::cluster.global.mbarrier::complete_tx::bytes [%0], [%1], %2, [%3];"
        :: "r"(dst), "l"(src), "r"(bytes), "r"(mbar) : "memory");
}

#define SMEM_SWIZZLE_128B(x) ((x) ^ (((x) >> 3) & 0x70))
// swizzle for 64-byte rows (V^T blocks): 16B chunk c within row r
__device__ __forceinline__ uint32_t swz64(int r, int c) {
    return (uint32_t)(r * 64 + ((c ^ ((r >> 1) & 3)) << 4));
}

#define LDSM4(r, addr) \
    asm volatile("ldmatrix.sync.aligned.m8n8.x4.shared.b16 {%0,%1,%2,%3}, [%4];" \
        : "=r"((r)[0]), "=r"((r)[1]), "=r"((r)[2]), "=r"((r)[3]) : "r"(addr))

__device__ __forceinline__ void mma16816(float* c, const uint32_t* a, uint32_t b0, uint32_t b1) {
    asm volatile("mma.sync.aligned.m16n8k16.row.col.f32.bf16.bf16.f32 "
        "{%0,%1,%2,%3}, {%4,%5,%6,%7}, {%8,%9}, {%0,%1,%2,%3};"
        : "+f"(c[0]), "+f"(c[1]), "+f"(c[2]), "+f"(c[3])
        : "r"(a[0]), "r"(a[1]), "r"(a[2]), "r"(a[3]), "r"(b0), "r"(b1));
}

__device__ __forceinline__ float ex2(float x) {
    float r;
    asm("ex2.approx.f32 %0, %1;" : "=f"(r) : "f"(x));
    return r;
}

__device__ __forceinline__ void split1(float v, __nv_bfloat16& h, __nv_bfloat16& l) {
    h = __float2bfloat16(v);
    l = __float2bfloat16(v - __bfloat162float(h));
}
__device__ __forceinline__ uint32_t pk2(float a, float b) {
    __nv_bfloat162 t = __floats2bfloat162_rn(a, b);
    return *(uint32_t*)&t;
}

// ---------------------------------------------------------------------------
// split fp32 row-major [4096][4096] -> tiled+swizzled bf16 hi/lo blocks (GEMM A)
// ---------------------------------------------------------------------------
__global__ void __launch_bounds__(256) split_rm_tiled(const float* __restrict__ in,
                                                      __nv_bfloat16* __restrict__ hi,
                                                      __nv_bfloat16* __restrict__ lo)
{
    size_t idx = (size_t)blockIdx.x * 256 + threadIdx.x;
    int m  = (int)(idx >> 9);
    int k  = (int)(idx & 511) << 3;
    const float4* p = (const float4*)(in + ((size_t)m << 12) + k);
    float4 v0 = p[0], v1 = p[1];

    __nv_bfloat16 h[8], l[8];
    split1(v0.x, h[0], l[0]); split1(v0.y, h[1], l[1]);
    split1(v0.z, h[2], l[2]); split1(v0.w, h[3], l[3]);
    split1(v1.x, h[4], l[4]); split1(v1.y, h[5], l[5]);
    split1(v1.z, h[6], l[6]); split1(v1.w, h[7], l[7]);

    int mt = m >> 7, r = m & 127, kt = k >> 6, c = k & 63;
    size_t base = ((size_t)mt * NKT + kt) * BLK_BYTES
                + SMEM_SWIZZLE_128B((uint32_t)(r * 128 + c * 2));
    *(uint4*)((char*)hi + base) = *(uint4*)h;
    *(uint4*)((char*)lo + base) = *(uint4*)l;
}

// ---------------------------------------------------------------------------
// W [K][N] fp32 -> BT tiled+swizzled bf16 hi/lo (transpose + split)
// ---------------------------------------------------------------------------
__global__ void __launch_bounds__(256) split_tr_tiled(const float* __restrict__ W,
                                                      __nv_bfloat16* __restrict__ Thi,
                                                      __nv_bfloat16* __restrict__ Tlo)
{
    __shared__ float t[32][33];
    int w = threadIdx.x;
    int nb = blockIdx.x * 32, kb = blockIdx.y * 32;
    int tx = w & 31, ty = w >> 5;
#pragma unroll
    for (int j = 0; j < 4; j++)
        t[ty + j * 8][tx] = W[(size_t)(kb + ty + j * 8) * DM + nb + tx];
    __syncthreads();

    int half = w >> 7, w7 = w & 127;
    int nn = w7 >> 2, kc = (w7 & 3) * 8;
    int n = nb + nn, kk = kb + kc;
    float v[8];
#pragma unroll
    for (int q = 0; q < 8; q++) v[q] = t[kc + q][nn];

    int nt = n >> 7, r = n & 127, kt = kk >> 6, c = kk & 63;
    size_t base = ((size_t)nt * NKT + kt) * BLK_BYTES
                + SMEM_SWIZZLE_128B((uint32_t)(r * 128 + c * 2));
    __nv_bfloat16 o[8];
    if (half == 0) {
#pragma unroll
        for (int q = 0; q < 8; q++) o[q] = __float2bfloat16(v[q]);
        *(uint4*)((char*)Thi + base) = *(uint4*)o;
    } else {
#pragma unroll
        for (int q = 0; q < 8; q++) {
            __nv_bfloat16 hh = __float2bfloat16(v[q]);
            o[q] = __float2bfloat16(v[q] - __bfloat162float(hh));
        }
        *(uint4*)((char*)Tlo + base) = *(uint4*)o;
    }
}

// ---------------------------------------------------------------------------
// HMMA split-bf16 GEMM, 3-stage pipeline with empty barriers.
// ---------------------------------------------------------------------------
__global__ void __launch_bounds__(256, 1) gemm_hmma(
    const __nv_bfloat16* __restrict__ Ahi, const __nv_bfloat16* __restrict__ Alo,
    const __nv_bfloat16* __restrict__ Bhi, const __nv_bfloat16* __restrict__ Blo,
    float* __restrict__ C, int mode)
{
    extern __shared__ char gsm[];
    uint32_t sb = (smem_to_u32(gsm) + 1023u) & ~1023u;
    const uint32_t stage0 = sb + 1024u;                   // 3 stages x 64KB
    const int tid = threadIdx.x, wid = tid >> 5, lane = tid & 31;
    const int bm = blockIdx.y * BM, bn = blockIdx.x * BN;
    const int wm = wid >> 2, wn = wid & 3;

    if (tid == 0) {
#pragma unroll
        for (int s = 0; s < 3; s++) {
            MBARRIER_INIT(sb + s * 8, 1);          // full
            MBARRIER_INIT(sb + 24 + s * 8, 256);   // empty
        }
        FENCE_PROXY_ASYNC();
    }
    __syncthreads();

    const char* pAh = (const char*)Ahi + ((size_t)blockIdx.y << 20);
    const char* pAl = (const char*)Alo + ((size_t)blockIdx.y << 20);
    const char* pBh = (const char*)Bhi + ((size_t)blockIdx.x << 20);
    const char* pBl = (const char*)Blo + ((size_t)blockIdx.x << 20);

    auto issue = [&](int j) {
        const int s = j % 3;
        const uint32_t st = stage0 + (uint32_t)s * 65536u;
        const uint32_t mb = sb + (uint32_t)s * 8u;
        const size_t off = (size_t)j << 14;
        MBARRIER_EXPECT_TX(mb, 65536u);
        tma_bulk(st,           pAh + off, 16384u, mb);
        tma_bulk(st + 16384u,  pAl + off, 16384u, mb);
        tma_bulk(st + 32768u,  pBh + off, 16384u, mb);
        tma_bulk(st + 49152u,  pBl + off, 16384u, mb);
    };
    if (tid == 0) { issue(0); issue(1); issue(2); }

    float acc[16][4];
#pragma unroll
    for (int i = 0; i < 16; i++)
#pragma unroll
        for (int j = 0; j < 4; j++) acc[i][j] = 0.f;

    const int ra = lane & 15, ca = (lane >> 4) * 16;
    const int rb = (lane & 7) + 8 * ((lane >> 3) & 1), cb = (lane >> 4) * 16;

    int fph[3] = {0, 0, 0};
    int eph[3] = {0, 0, 0};
    for (int i = 0; i < NKT; i++) {
        const int s = i % 3;
        const uint32_t st = stage0 + (uint32_t)s * 65536u;
        MBARRIER_WAIT_PARITY(sb + s * 8, fph[s]); fph[s] ^= 1;

#pragma unroll
        for (int ks = 0; ks < 4; ks++) {
            uint32_t ah[4][4], al[4][4], bh[2][4], bl[2][4];
#pragma unroll
            for (int im = 0; im < 4; im++) {
                uint32_t off = SMEM_SWIZZLE_128B(
                    (uint32_t)((wm * 64 + im * 16 + ra) * 128 + ks * 32 + ca));
                LDSM4(ah[im], st + off);
                LDSM4(al[im], st + 16384u + off);
            }
#pragma unroll
            for (int ip = 0; ip < 2; ip++) {
                uint32_t off = SMEM_SWIZZLE_128B(
                    (uint32_t)((wn * 32 + ip * 16 + rb) * 128 + ks * 32 + cb));
                LDSM4(bh[ip], st + 32768u + off);
                LDSM4(bl[ip], st + 49152u + off);
            }
#pragma unroll
            for (int im = 0; im < 4; im++)
#pragma unroll
                for (int in = 0; in < 4; in++) {
                    const int ip = in >> 1, sel = in & 1;
                    float* c = acc[im * 4 + in];
                    mma16816(c, ah[im], bh[ip][sel], bh[ip][sel + 2]);
                    mma16816(c, ah[im], bl[ip][sel], bl[ip][sel + 2]);
                    mma16816(c, al[im], bh[ip][sel], bh[ip][sel + 2]);
                }
        }
        MBARRIER_ARRIVE(sb + 24 + s * 8);
        if (tid == 0 && i + 3 < NKT) {
            MBARRIER_WAIT_PARITY(sb + 24 + s * 8, eph[s]); eph[s] ^= 1;
            issue(i + 3);
        }
    }

#pragma unroll
    for (int im = 0; im < 4; im++) {
#pragma unroll
        for (int in = 0; in < 4; in++) {
            const float* c = acc[im * 4 + in];
            int m0 = bm + wm * 64 + im * 16 + (lane >> 2);
            int n  = bn + wn * 32 + in * 8 + (lane & 3) * 2;
#pragma unroll
            for (int half = 0; half < 2; half++) {
                int m = m0 + half * 8;
                float2 v = half ? make_float2(c[2], c[3]) : make_float2(c[0], c[1]);
                if (mode == 0) {
                    *(float2*)(C + (size_t)m * DM + n) = v;
                } else {
                    int b = m >> 11, sq = m & 2047, h = n >> 8, hd = n & 255;
                    *(float2*)(C + ((size_t)(b * NH + h) * SEQ + sq) * HDIM + hd) = v;
                }
            }
        }
    }
}

// ---------------------------------------------------------------------------
// RoPE (GPT-J interleaved)
// ---------------------------------------------------------------------------
__global__ void __launch_bounds__(256) rope_kernel(float* __restrict__ Q, float* __restrict__ K,
                                                   const int* __restrict__ pos)
{
    int idx = blockIdx.x * blockDim.x + threadIdx.x;
    if (idx >= SEQ * 32) return;
    int i = idx & 31, s = idx >> 5;
    double inv = pow(10000.0, -(double)(2 * i) / (double)ROTD);
#pragma unroll
    for (int b = 0; b < MB; b++) {
        int p = pos[b * SEQ + s];
        double sn_, cs_;
        sincos((double)p * inv, &sn_, &cs_);
        float sn = (float)sn_, cs = (float)cs_;
#pragma unroll
        for (int h = 0; h < NH; h++) {
            size_t base = ((size_t)(b * NH + h) * SEQ + s) * HDIM + 2 * i;
            float2 q = *(float2*)(Q + base);
            *(float2*)(Q + base) = make_float2(q.x * cs - q.y * sn, q.y * cs + q.x * sn);
            float2 k = *(float2*)(K + base);
            *(float2*)(K + base) = make_float2(k.x * cs - k.y * sn, k.y * cs + k.x * sn);
        }
    }
}

// ---------------------------------------------------------------------------
// pack Q and K (fp32 [B,H,S,HD]) -> bf16 hi/lo blocked images
// block layout: [bh][st=s/32][ct=c/64][32][64], SW128, 4KB blocks
// ---------------------------------------------------------------------------
__global__ void __launch_bounds__(256) pack_qk(const float* __restrict__ Q, const float* __restrict__ K,
                                               __nv_bfloat16* __restrict__ Qh, __nv_bfloat16* __restrict__ Ql,
                                               __nv_bfloat16* __restrict__ Kh, __nv_bfloat16* __restrict__ Kl)
{
    size_t idx = (size_t)blockIdx.x * 256 + threadIdx.x;   // 2,097,152
    int c0 = (int)(idx & 31) << 3;
    int s  = (int)(idx >> 5) & 2047;
    int bh = (int)(idx >> 16);

    int st = s >> 5, r = s & 31, ct = c0 >> 6, cc = c0 & 63;
    size_t dst = (((size_t)(bh * 64 + st) * 4 + ct) << 12)
               + SMEM_SWIZZLE_128B((uint32_t)(r * 128 + cc * 2));
    size_t src = ((size_t)bh * SEQ + s) * HDIM + c0;

    {
        const float4* p = (const float4*)(Q + src);
        float4 v0 = p[0], v1 = p[1];
        float vv[8] = {v0.x, v0.y, v0.z, v0.w, v1.x, v1.y, v1.z, v1.w};
        __nv_bfloat16 h[8], l[8];
#pragma unroll
        for (int q = 0; q < 8; q++) split1(vv[q], h[q], l[q]);
        *(uint4*)((char*)Qh + dst) = *(uint4*)h;
        *(uint4*)((char*)Ql + dst) = *(uint4*)l;
    }
    {
        const float4* p = (const float4*)(K + src);
        float4 v0 = p[0], v1 = p[1];
        float vv[8] = {v0.x, v0.y, v0.z, v0.w, v1.x, v1.y, v1.z, v1.w};
        __nv_bfloat16 h[8], l[8];
#pragma unroll
        for (int q = 0; q < 8; q++) split1(vv[q], h[q], l[q]);
        *(uint4*)((char*)Kh + dst) = *(uint4*)h;
        *(uint4*)((char*)Kl + dst) = *(uint4*)l;
    }
}

// ---------------------------------------------------------------------------
// pack V transposed: fp32 [B,H,S,HD] -> Vt bf16 hi/lo
// block layout: [bh][jt=s/32][dt=d/128][128 rows(d)][32 cols(j)], swz64, 8KB blocks
// ---------------------------------------------------------------------------
__global__ void __launch_bounds__(256) pack_v(const float* __restrict__ V,
                                              __nv_bfloat16* __restrict__ Vh, __nv_bfloat16* __restrict__ Vl)
{
    __shared__ float sm[32][257];
    int jt = blockIdx.x, bh = blockIdx.y;
    int t = threadIdx.x;
    int r = t >> 3, d0 = (t & 7) * 32;
    const float* src = V + ((size_t)bh * SEQ + jt * 32 + r) * HDIM + d0;
#pragma unroll
    for (int i = 0; i < 8; i++) {
        float4 v = *(const float4*)(src + i * 4);
        sm[r][d0 + i * 4 + 0] = v.x; sm[r][d0 + i * 4 + 1] = v.y;
        sm[r][d0 + i * 4 + 2] = v.z; sm[r][d0 + i * 4 + 3] = v.w;
    }
    __syncthreads();

    int d = t;                       // 0..255
    int dt = d >> 7, rd = d & 127;
    size_t base = ((size_t)(bh * 64 + jt) * 2 + dt) << 13;
#pragma unroll
    for (int c = 0; c < 4; c++) {
        __nv_bfloat16 h[8], l[8];
#pragma unroll
        for (int jj = 0; jj < 8; jj++) split1(sm[c * 8 + jj][d], h[jj], l[jj]);
        size_t off = base + swz64(rd, c);
        *(uint4*)((char*)Vh + off) = *(uint4*)h;
        *(uint4*)((char*)Vl + off) = *(uint4*)l;
    }
}

// ---------------------------------------------------------------------------
// HMMA causal flash attention, split-bf16, online softmax.
// CTA: q-tile 64 (4 warps x 16 rows), k-tiles of 32 double-buffered.
// ---------------------------------------------------------------------------
__global__ void __launch_bounds__(128, 1) attn_mma(
    const __nv_bfloat16* __restrict__ Qph, const __nv_bfloat16* __restrict__ Qpl,
    const __nv_bfloat16* __restrict__ Kph, const __nv_bfloat16* __restrict__ Kpl,
    const __nv_bfloat16* __restrict__ Vph, const __nv_bfloat16* __restrict__ Vpl,
    float* __restrict__ CTX)
{
    extern __shared__ char gsm[];
    uint32_t sb = (smem_to_u32(gsm) + 1023u) & ~1023u;
    const uint32_t sq = sb + 1024u;            // Q: hi 32KB @sq, lo 32KB @sq+32768
    const uint32_t sv = sq + 65536u;           // 2 stages x 64KB: Kh,Kl,Vh,Vl (16KB each)

    const int qt = (int)gridDim.x - 1 - (int)blockIdx.x;   // high-work CTAs first
    const int bh = blockIdx.y;
    const int b  = bh >> 4, h = bh & 15;
    const int tid = threadIdx.x, w = tid >> 5, lane = tid & 31;
    const int nkt = 2 * qt + 2;

    if (tid == 0) {
        MBARRIER_INIT(sb, 1);                    // Q barrier
        MBARRIER_INIT(sb + 8, 1);                // full0
        MBARRIER_INIT(sb + 16, 1);               // full1
        MBARRIER_INIT(sb + 24, 128);             // empty0
        MBARRIER_INIT(sb + 32, 128);             // empty1
        FENCE_PROXY_ASYNC();
    }
    __syncthreads();

    auto issueKV = [&](int kt, int s) {
        const uint32_t st = sv + (uint32_t)s * 65536u;
        const uint32_t mb = sb + 8 + (uint32_t)s * 8u;
        MBARRIER_EXPECT_TX(mb, 65536u);
        size_t kbase = ((size_t)(bh * 64 + kt) * 4) << 12;
#pragma unroll
        for (int ct = 0; ct < 4; ct++) {
            tma_bulk(st + ct * 4096,          (const char*)Kph + kbase + ct * 4096, 4096u, mb);
            tma_bulk(st + 16384 + ct * 4096,  (const char*)Kpl + kbase + ct * 4096, 4096u, mb);
        }
        size_t vbase = ((size_t)(bh * 64 + kt) * 2) << 13;
#pragma unroll
        for (int dt = 0; dt < 2; dt++) {
            tma_bulk(st + 32768 + dt * 8192,  (const char*)Vph + vbase + dt * 8192, 8192u, mb);
            tma_bulk(st + 49152 + dt * 8192,  (const char*)Vpl + vbase + dt * 8192, 8192u, mb);
        }
    };

    if (tid == 0) {
        MBARRIER_EXPECT_TX(sb, 65536u);
#pragma unroll
        for (int sb2 = 0; sb2 < 2; sb2++) {
            size_t qbase = ((size_t)(bh * 64 + qt * 2 + sb2) * 4) << 12;
#pragma unroll
            for (int ct = 0; ct < 4; ct++) {
                tma_bulk(sq + (sb2 * 4 + ct) * 4096,          (const char*)Qph + qbase + ct * 4096, 4096u, sb);
                tma_bulk(sq + 32768 + (sb2 * 4 + ct) * 4096,  (const char*)Qpl + qbase + ct * 4096, 4096u, sb);
            }
        }
        issueKV(0, 0);
        issueKV(1, 1);
    }

    float out[32][4];
#pragma unroll
    for (int i = 0; i < 32; i++)
#pragma unroll
        for (int j = 0; j < 4; j++) out[i][j] = 0.f;
    float m0 = -1e30f, m1 = -1e30f, l0 = 0.f, l1 = 0.f;

    const int ra = lane & 15;
    const int rb = (lane & 7) + 8 * ((lane >> 3) & 1);
    const int qrow = (w & 1) * 16 + ra;                  // local row within 32-row block
    const int row0g = qt * 64 + w * 16 + (lane >> 2);    // global rows
    const int row1g = row0g + 8;
    const float SC = 0.0901699438f;                      // (1/16) * log2(e)

    MBARRIER_WAIT_PARITY(sb, 0);                         // Q resident

    int fph0 = 0, fph1 = 0, eph0 = 0, eph1 = 0;
    for (int kt = 0; kt < nkt; kt++) {
        const int s = kt & 1;
        const uint32_t st = sv + (uint32_t)s * 65536u;
        if (s == 0) { MBARRIER_WAIT_PARITY(sb + 8, fph0);  fph0 ^= 1; }
        else        { MBARRIER_WAIT_PARITY(sb + 16, fph1); fph1 ^= 1; }

        // ---- scores = Q x K^T (32 keys), 3 split products ----
        float sc[4][4];
#pragma unroll
        for (int f = 0; f < 4; f++)
#pragma unroll
            for (int j = 0; j < 4; j++) sc[f][j] = 0.f;

#pragma unroll
        for (int kk = 0; kk < 16; kk++) {
            uint32_t ah[4], al[4], kh[2][4], kl[2][4];
            uint32_t aoff = (uint32_t)(((w >> 1) * 4 + (kk >> 2)) * 4096)
                          + SMEM_SWIZZLE_128B((uint32_t)(qrow * 128 + (kk & 3) * 32 + (lane >> 4) * 16));
            LDSM4(ah, sq + aoff);
            LDSM4(al, sq + 32768u + aoff);
#pragma unroll
            for (int ip = 0; ip < 2; ip++) {
                uint32_t koff = (uint32_t)((kk >> 2) * 4096)
                              + SMEM_SWIZZLE_128B((uint32_t)((ip * 16 + rb) * 128 + (kk & 3) * 32 + (lane >> 4) * 16));
                LDSM4(kh[ip], st + koff);
                LDSM4(kl[ip], st + 16384u + koff);
            }
#pragma unroll
            for (int f = 0; f < 4; f++) {
                const int ip = f >> 1, sel = f & 1;
                mma16816(sc[f], ah, kh[ip][sel], kh[ip][sel + 2]);
                mma16816(sc[f], ah, kl[ip][sel], kl[ip][sel + 2]);
                mma16816(sc[f], al, kh[ip][sel], kh[ip][sel + 2]);
            }
        }

        // ---- online softmax over this 32-key tile ----
        const bool domask = (kt * 32 + 31) > (qt * 64 + w * 16);
        float tm0 = -1e30f, tm1 = -1e30f;
#pragma unroll
        for (int f = 0; f < 4; f++) {
#pragma unroll
            for (int j = 0; j < 4; j++) {
                float v = sc[f][j] * SC;
                if (domask) {
                    int col = kt * 32 + f * 8 + (lane & 3) * 2 + (j & 1);
                    int row = (j < 2) ? row0g : row1g;
                    if (col > row) v = -1e30f;
                }
                sc[f][j] = v;
                if (j < 2) tm0 = fmaxf(tm0, v); else tm1 = fmaxf(tm1, v);
            }
        }
        tm0 = fmaxf(tm0, __shfl_xor_sync(0xffffffffu, tm0, 1));
        tm0 = fmaxf(tm0, __shfl_xor_sync(0xffffffffu, tm0, 2));
        tm1 = fmaxf(tm1, __shfl_xor_sync(0xffffffffu, tm1, 1));
        tm1 = fmaxf(tm1, __shfl_xor_sync(0xffffffffu, tm1, 2));
        float nm0 = fmaxf(m0, tm0), nm1 = fmaxf(m1, tm1);
        float a0 = ex2(m0 - nm0), a1 = ex2(m1 - nm1);
        float ls0 = 0.f, ls1 = 0.f;
#pragma unroll
        for (int f = 0; f < 4; f++) {
            sc[f][0] = ex2(sc[f][0] - nm0); ls0 += sc[f][0];
            sc[f][1] = ex2(sc[f][1] - nm0); ls0 += sc[f][1];
            sc[f][2] = ex2(sc[f][2] - nm1); ls1 += sc[f][2];
            sc[f][3] = ex2(sc[f][3] - nm1); ls1 += sc[f][3];
        }
        ls0 += __shfl_xor_sync(0xffffffffu, ls0, 1);
        ls0 += __shfl_xor_sync(0xffffffffu, ls0, 2);
        ls1 += __shfl_xor_sync(0xffffffffu, ls1, 1);
        ls1 += __shfl_xor_sync(0xffffffffu, ls1, 2);
        l0 = l0 * a0 + ls0; l1 = l1 * a1 + ls1;
        m0 = nm0; m1 = nm1;

#pragma unroll
        for (int i = 0; i < 32; i++) {
            out[i][0] *= a0; out[i][1] *= a0;
            out[i][2] *= a1; out[i][3] *= a1;
        }

        // ---- P frags (bf16 hi/lo) ----
        uint32_t pah[2][4], pal[2][4];
#pragma unroll
        for (int kc = 0; kc < 2; kc++) {
            float* f0 = sc[2 * kc];
            float* f1 = sc[2 * kc + 1];
            pah[kc][0] = pk2(f0[0], f0[1]);
            pah[kc][1] = pk2(f0[2], f0[3]);
            pah[kc][2] = pk2(f1[0], f1[1]);
            pah[kc][3] = pk2(f1[2], f1[3]);
            float r00 = f0[0] - __bfloat162float(__float2bfloat16(f0[0]));
            float r01 = f0[1] - __bfloat162float(__float2bfloat16(f0[1]));
            float r02 = f0[2] - __bfloat162float(__float2bfloat16(f0[2]));
            float r03 = f0[3] - __bfloat162float(__float2bfloat16(f0[3]));
            float r10 = f1[0] - __bfloat162float(__float2bfloat16(f1[0]));
            float r11 = f1[1] - __bfloat162float(__float2bfloat16(f1[1]));
            float r12 = f1[2] - __bfloat162float(__float2bfloat16(f1[2]));
            float r13 = f1[3] - __bfloat162float(__float2bfloat16(f1[3]));
            pal[kc][0] = pk2(r00, r01);
            pal[kc][1] = pk2(r02, r03);
            pal[kc][2] = pk2(r10, r11);
            pal[kc][3] = pk2(r12, r13);
        }

        // ---- out += P x V^T ----
#pragma unroll
        for (int kc = 0; kc < 2; kc++) {
#pragma unroll
            for (int dp = 0; dp < 16; dp++) {
                uint32_t vh[4], vl[4];
                int rr = (dp & 7) * 16 + rb;
                uint32_t voff = (uint32_t)((dp >> 3) * 8192) + swz64(rr, kc * 2 + (lane >> 4));
                LDSM4(vh, st + 32768u + voff);
                LDSM4(vl, st + 49152u + voff);
#pragma unroll
                for (int sel = 0; sel < 2; sel++) {
                    float* c = out[2 * dp + sel];
                    mma16816(c, pah[kc], vh[sel], vh[sel + 2]);
                    mma16816(c, pah[kc], vl[sel], vl[sel + 2]);
                    mma16816(c, pal[kc], vh[sel], vh[sel + 2]);
                }
            }
        }

        MBARRIER_ARRIVE(sb + 24 + s * 8);
        if (tid == 0 && kt + 2 < nkt) {
            if (s == 0) { MBARRIER_WAIT_PARITY(sb + 24, eph0); eph0 ^= 1; }
            else        { MBARRIER_WAIT_PARITY(sb + 32, eph1); eph1 ^= 1; }
            issueKV(kt + 2, s);
        }
    }

    // ---- epilogue: out / l -> CTX [B,S,D] ----
    float inv0 = 1.0f / l0, inv1 = 1.0f / l1;
    float* base0 = CTX + ((size_t)(b * SEQ + row0g)) * DM + h * HDIM;
    float* base1 = CTX + ((size_t)(b * SEQ + row1g)) * DM + h * HDIM;
#pragma unroll
    for (int nf = 0; nf < 32; nf++) {
        int d = nf * 8 + (lane & 3) * 2;
        *(float2*)(base0 + d) = make_float2(out[nf][0] * inv0, out[nf][1] * inv0);
        *(float2*)(base1 + d) = make_float2(out[nf][2] * inv1, out[nf][3] * inv1);
    }
}

// ---------------------------------------------------------------------------
extern "C" void kernel_launch(void* const* d_in, const int* in_sizes, int n_in,
                              void* d_out, int out_size)
{
    const float* X   = (const float*)d_in[0];
    const int*   pos = (const int*)  d_in[1];
    const float* W[4] = { (const float*)d_in[2], (const float*)d_in[3],
                          (const float*)d_in[4], (const float*)d_in[5] };
    float* out = (float*)d_out;

    float *Qg, *Kg, *Vg, *CTX;
    __nv_bfloat16 *Xhi, *Xlo, *Chi, *Clo, *WThi, *WTlo;
    __nv_bfloat16 *Qph, *Qpl, *Kph, *Kpl, *Vph, *Vpl;
    cudaGetSymbolAddress((void**)&Qg,  g_Q);
    cudaGetSymbolAddress((void**)&Kg,  g_K);
    cudaGetSymbolAddress((void**)&Vg,  g_V);
    cudaGetSymbolAddress((void**)&CTX, g_CTX);
    cudaGetSymbolAddress((void**)&Xhi, g_Xhi);
    cudaGetSymbolAddress((void**)&Xlo, g_Xlo);
    cudaGetSymbolAddress((void**)&Chi, g_Chi);
    cudaGetSymbolAddress((void**)&Clo, g_Clo);
    cudaGetSymbolAddress((void**)&WThi, g_WThi);
    cudaGetSymbolAddress((void**)&WTlo, g_WTlo);
    cudaGetSymbolAddress((void**)&Qph, g_Qph);
    cudaGetSymbolAddress((void**)&Qpl, g_Qpl);
    cudaGetSymbolAddress((void**)&Kph, g_Kph);
    cudaGetSymbolAddress((void**)&Kpl, g_Kpl);
    cudaGetSymbolAddress((void**)&Vph, g_Vph);
    cudaGetSymbolAddress((void**)&Vpl, g_Vpl);

    const int GEMM_SMEM = 1024 + 1024 + 3 * 65536;   // 198656
    const int ATTN_SMEM = 1024 + 1024 + 65536 + 2 * 65536;  // 198656
    cudaFuncSetAttribute(gemm_hmma, cudaFuncAttributeMaxDynamicSharedMemorySize, GEMM_SMEM);
    cudaFuncSetAttribute(attn_mma, cudaFuncAttributeMaxDynamicSharedMemorySize, ATTN_SMEM);

    const size_t WSZ = (size_t)DM * DM;
    dim3 trg(DM / 32, DM / 32);
    dim3 gg(DM / BN, DM / BM);   // 32 x 32

    // pack GEMM operands
    split_rm_tiled<<<8192, 256>>>(X, Xhi, Xlo);
    for (int w = 0; w < 4; w++)
        split_tr_tiled<<<trg, 256>>>(W[w], WThi + (size_t)w * WSZ, WTlo + (size_t)w * WSZ);

    // QKV projections (scatter to [B,H,S,HD] fp32)
    gemm_hmma<<<gg, 256, GEMM_SMEM>>>(Xhi, Xlo, WThi + 0 * WSZ, WTlo + 0 * WSZ, Qg, 1);
    gemm_hmma<<<gg, 256, GEMM_SMEM>>>(Xhi, Xlo, WThi + 1 * WSZ, WTlo + 1 * WSZ, Kg, 1);
    gemm_hmma<<<gg, 256, GEMM_SMEM>>>(Xhi, Xlo, WThi + 2 * WSZ, WTlo + 2 * WSZ, Vg, 1);

    rope_kernel<<<(SEQ * 32 + 255) / 256, 256>>>(Qg, Kg, pos);

    // pack attention operands
    pack_qk<<<8192, 256>>>(Qg, Kg, Qph, Qpl, Kph, Kpl);
    pack_v<<<dim3(64, 32), 256>>>(Vg, Vph, Vpl);

    // attention
    attn_mma<<<dim3(32, 32), 128, ATTN_SMEM>>>(Qph, Qpl, Kph, Kpl, Vph, Vpl, CTX);

    // output projection
    split_rm_tiled<<<8192, 256>>>(CTX, Chi, Clo);
    gemm_hmma<<<gg, 256, GEMM_SMEM>>>(Chi, Clo, WThi + 3 * WSZ, WTlo + 3 * WSZ, out, 0);
}